// round 5
// baseline (speedup 1.0000x reference)
#include <cuda_runtime.h>

#define Lc 1024
#define Bc 256
#define Dc 256
#define Tc 50
#define Hc 8
#define DHc 32

#define MEAN_CH 16  // L-chunks for mean pass
#define FL_CH 16    // L-chunks for flash pass (64 rows each)

// Scratch (allocation-free rule: __device__ globals)
__device__ float g_hbar_part[MEAN_CH][Bc*Dc];
__device__ float g_qk[Bc*Hc*Dc];                // [b][h][i], includes 1/sqrt(32)
__device__ float g_wE_part[FL_CH][Bc*Hc*Dc];    // unnormalized partial [b][h][i]
__device__ float2 g_ms[Bc*FL_CH*Hc];            // (m, s) per (b, chunk, h)
__device__ float g_qk2[Bc*Dc];                  // [b][i], includes 1/sqrt(256)
__device__ float g_fs[Bc*Lc];                   // [b][l]

__device__ __forceinline__ unsigned long long f2ull(float x, float y) {
    unsigned long long u;
    asm("mov.b64 %0, {%1,%2};" : "=l"(u) : "f"(x), "f"(y));
    return u;
}
__device__ __forceinline__ float2 ull2f2(unsigned long long u) {
    float2 f;
    asm("mov.b64 {%0,%1}, %2;" : "=f"(f.x), "=f"(f.y) : "l"(u));
    return f;
}
__device__ __forceinline__ void fma2(unsigned long long& acc, unsigned long long a, unsigned long long b) {
    asm("fma.rn.f32x2 %0, %1, %2, %3;" : "=l"(acc) : "l"(a), "l"(b), "l"(acc));
}
__device__ __forceinline__ void cp_async16(unsigned int saddr, const void* g) {
    asm volatile("cp.async.cg.shared.global [%0], [%1], 16;" :: "r"(saddr), "l"(g));
}

// 8-value fold reduction: lanes with lane%4==0 hold full sum for head (lane>>2). 9 shuffles.
__device__ __forceinline__ float fold8(const float sc[8], int lane) {
    bool hi16 = (lane & 16) != 0;
    float n[4];
    #pragma unroll
    for (int k = 0; k < 4; k++) {
        float give = hi16 ? sc[k] : sc[4 + k];
        float keep = hi16 ? sc[4 + k] : sc[k];
        n[k] = keep + __shfl_xor_sync(0xffffffffu, give, 16);
    }
    bool hi8 = (lane & 8) != 0;
    float m[2];
    #pragma unroll
    for (int j = 0; j < 2; j++) {
        float give = hi8 ? n[j] : n[2 + j];
        float keep = hi8 ? n[2 + j] : n[j];
        m[j] = keep + __shfl_xor_sync(0xffffffffu, give, 8);
    }
    bool hi4 = (lane & 4) != 0;
    float give = hi4 ? m[0] : m[1];
    float keep = hi4 ? m[1] : m[0];
    float v = keep + __shfl_xor_sync(0xffffffffu, give, 4);
    v += __shfl_xor_sync(0xffffffffu, v, 1);
    v += __shfl_xor_sync(0xffffffffu, v, 2);
    return v;
}

// 4-value fold: lanes with lane%8==0 hold row (lane>>3).
__device__ __forceinline__ float fold4(const float r[4], int lane) {
    bool hi16 = (lane & 16) != 0;
    float n[2];
    #pragma unroll
    for (int j = 0; j < 2; j++) {
        float give = hi16 ? r[j] : r[2 + j];
        float keep = hi16 ? r[2 + j] : r[j];
        n[j] = keep + __shfl_xor_sync(0xffffffffu, give, 16);
    }
    bool hi8 = (lane & 8) != 0;
    float give = hi8 ? n[0] : n[1];
    float keep = hi8 ? n[1] : n[0];
    float v = keep + __shfl_xor_sync(0xffffffffu, give, 8);
    v += __shfl_xor_sync(0xffffffffu, v, 4);
    v += __shfl_xor_sync(0xffffffffu, v, 2);
    v += __shfl_xor_sync(0xffffffffu, v, 1);
    return v;
}

// ---------------- Pass 1: partial sums for hbar. grid (64, MEAN_CH), block 256 ----------------
__global__ void k_mean_part(const float* __restrict__ ebp) {
    int cg = blockIdx.x * 256 + threadIdx.x;
    int l0 = blockIdx.y * (Lc / MEAN_CH);
    const float4* p = (const float4*)ebp + (size_t)l0 * (Bc * Dc / 4) + cg;
    float4 a0 = {0,0,0,0}, a1 = {0,0,0,0}, a2 = {0,0,0,0}, a3 = {0,0,0,0};
    #pragma unroll 2
    for (int l = 0; l < Lc / MEAN_CH; l += 8) {
        float4 v0 = p[(size_t)(l + 0) * (Bc * Dc / 4)];
        float4 v1 = p[(size_t)(l + 1) * (Bc * Dc / 4)];
        float4 v2 = p[(size_t)(l + 2) * (Bc * Dc / 4)];
        float4 v3 = p[(size_t)(l + 3) * (Bc * Dc / 4)];
        float4 v4 = p[(size_t)(l + 4) * (Bc * Dc / 4)];
        float4 v5 = p[(size_t)(l + 5) * (Bc * Dc / 4)];
        float4 v6 = p[(size_t)(l + 6) * (Bc * Dc / 4)];
        float4 v7 = p[(size_t)(l + 7) * (Bc * Dc / 4)];
        a0.x += v0.x; a0.y += v0.y; a0.z += v0.z; a0.w += v0.w;
        a1.x += v1.x; a1.y += v1.y; a1.z += v1.z; a1.w += v1.w;
        a2.x += v2.x; a2.y += v2.y; a2.z += v2.z; a2.w += v2.w;
        a3.x += v3.x; a3.y += v3.y; a3.z += v3.z; a3.w += v3.w;
        a0.x += v4.x; a0.y += v4.y; a0.z += v4.z; a0.w += v4.w;
        a1.x += v5.x; a1.y += v5.y; a1.z += v5.z; a1.w += v5.w;
        a2.x += v6.x; a2.y += v6.y; a2.z += v6.z; a2.w += v6.w;
        a3.x += v7.x; a3.y += v7.y; a3.z += v7.z; a3.w += v7.w;
    }
    float4 r;
    r.x = (a0.x + a1.x) + (a2.x + a3.x);
    r.y = (a0.y + a1.y) + (a2.y + a3.y);
    r.z = (a0.z + a1.z) + (a2.z + a3.z);
    r.w = (a0.w + a1.w) + (a2.w + a3.w);
    ((float4*)g_hbar_part[blockIdx.y])[cg] = r;
}

// ---------------- q1 + qk fused, 4 b's per block, grid 64 ----------------
__global__ void __launch_bounds__(256) k_q1qk(const float* __restrict__ ebp,
                                              const int* __restrict__ pa,
                                              const float* __restrict__ Wq1,
                                              const float* __restrict__ Wk1) {
    int bs = blockIdx.x * 4, t = threadIdx.x;
    __shared__ float ctx[4][3 * Dc];    // 12KB
    __shared__ float q1s[4][Dc];        // 4KB
    #pragma unroll
    for (int j = 0; j < 4; j++) {
        float hs = 0.f;
        #pragma unroll
        for (int c = 0; c < MEAN_CH; c++) hs += g_hbar_part[c][(bs + j) * Dc + t];
        ctx[j][t] = hs * (1.0f / Lc);
        int aL = pa[(bs + j) * Tc + (Tc - 1)];
        int a0 = pa[(bs + j) * Tc];
        ctx[j][Dc + t]     = ebp[((size_t)aL * Bc + bs + j) * Dc + t];
        ctx[j][2 * Dc + t] = ebp[((size_t)a0 * Bc + bs + j) * Dc + t];
    }
    __syncthreads();
    {
        float a0 = 0.f, a1 = 0.f, a2 = 0.f, a3 = 0.f;
        #pragma unroll 4
        for (int i = 0; i < 3 * Dc; i++) {
            float w = Wq1[i * Dc + t];
            a0 = fmaf(ctx[0][i], w, a0);
            a1 = fmaf(ctx[1][i], w, a1);
            a2 = fmaf(ctx[2][i], w, a2);
            a3 = fmaf(ctx[3][i], w, a3);
        }
        q1s[0][t] = a0; q1s[1][t] = a1; q1s[2][t] = a2; q1s[3][t] = a3;
    }
    __syncthreads();
    // qk: thread t = output i
    #pragma unroll
    for (int h = 0; h < Hc; h++) {
        float a0 = 0.f, a1 = 0.f, a2 = 0.f, a3 = 0.f;
        #pragma unroll
        for (int d = 0; d < DHc; d++) {
            float w = Wk1[t * Dc + h * DHc + d];
            a0 = fmaf(q1s[0][h * DHc + d], w, a0);
            a1 = fmaf(q1s[1][h * DHc + d], w, a1);
            a2 = fmaf(q1s[2][h * DHc + d], w, a2);
            a3 = fmaf(q1s[3][h * DHc + d], w, a3);
        }
        const float sc = 0.17677669529663687f;  // 1/sqrt(32)
        g_qk[((bs + 0) * Hc + h) * Dc + t] = a0 * sc;
        g_qk[((bs + 1) * Hc + h) * Dc + t] = a1 * sc;
        g_qk[((bs + 2) * Hc + h) * Dc + t] = a2 * sc;
        g_qk[((bs + 3) * Hc + h) * Dc + t] = a3 * sc;
    }
}

// ---------------- Fused flash pass: cp.async stage + score + exact chunk softmax + accumulate ----
// grid (Bc, FL_CH), block 256 (8 warps), 64 rows per block, dynamic smem 67712B.
__global__ void __launch_bounds__(256, 2) k_flash(const float* __restrict__ ebp,
                                                  const int* __restrict__ pa) {
    extern __shared__ float smem[];
    float* tile = smem;                       // [64][256] floats = 65536B
    float* wsc  = smem + 64 * 256;            // [64][8] floats  = 2048B
    unsigned* mb = (unsigned*)(wsc + 64 * 8); // 128B
    int b = blockIdx.x, cy = blockIdx.y, t = threadIdx.x;
    int warp = t >> 5, lane = t & 31;
    int l0 = cy * 64;

    if (t < 32) mb[t] = 0u;
    // stage 64 rows into smem: thread t copies 256B of row t>>2
    {
        int r = t >> 2, part = t & 3;
        const float* grow = ebp + ((size_t)(l0 + r) * Bc + b) * Dc + part * 64;
        unsigned int sa = (unsigned int)__cvta_generic_to_shared(tile + r * 256 + part * 64);
        #pragma unroll
        for (int k = 0; k < 16; k++) cp_async16(sa + k * 16, grow + k * 4);
        asm volatile("cp.async.commit_group;");
    }
    __syncthreads();   // mb zero visible
    if (t < Tc) {
        int a = pa[b * Tc + t];
        atomicOr(&mb[a >> 5], 1u << (a & 31));
    }

    // load qk while cp.async in flight
    unsigned long long qkp[Hc][4];
    {
        const ulonglong2* qb = (const ulonglong2*)(g_qk + b * Hc * Dc);
        #pragma unroll
        for (int h = 0; h < Hc; h++) {
            ulonglong2 u0 = qb[h * (Dc / 4) + lane * 2];
            ulonglong2 u1 = qb[h * (Dc / 4) + lane * 2 + 1];
            qkp[h][0] = u0.x; qkp[h][1] = u0.y; qkp[h][2] = u1.x; qkp[h][3] = u1.y;
        }
    }
    asm volatile("cp.async.wait_group 0;" ::: "memory");
    __syncthreads();

    // score phase: warp w rows w*8 .. w*8+7
    #pragma unroll
    for (int j = 0; j < 8; j++) {
        int r = warp * 8 + j;
        const ulonglong2* rp = (const ulonglong2*)(tile + r * 256) + lane * 2;
        ulonglong2 A = rp[0], B = rp[1];
        unsigned long long e[4] = {A.x, A.y, B.x, B.y};
        float sc[Hc];
        #pragma unroll
        for (int h = 0; h < Hc; h++) {
            unsigned long long acc = 0ull;
            #pragma unroll
            for (int q = 0; q < 4; q++) fma2(acc, e[q], qkp[h][q]);
            float2 f = ull2f2(acc);
            sc[h] = f.x + f.y;
        }
        float v = fold8(sc, lane);
        if ((lane & 3) == 0) {
            int h = lane >> 2;
            int l = l0 + r;
            bool m = (mb[l >> 5] >> (l & 31)) & 1u;
            wsc[r * 8 + h] = m ? -1e4f : v;
        }
    }
    __syncthreads();

    // exact chunk softmax: warp h handles head h (64 scores)
    if (warp < 8) {
        int h = warp;
        float lv0 = wsc[lane * 8 + h];
        float lv1 = wsc[(lane + 32) * 8 + h];
        float m = fmaxf(lv0, lv1);
        #pragma unroll
        for (int o = 16; o > 0; o >>= 1) m = fmaxf(m, __shfl_xor_sync(0xffffffffu, m, o));
        float w0 = __expf(lv0 - m), w1 = __expf(lv1 - m);
        float s = w0 + w1;
        #pragma unroll
        for (int o = 16; o > 0; o >>= 1) s += __shfl_xor_sync(0xffffffffu, s, o);
        wsc[lane * 8 + h] = w0;
        wsc[(lane + 32) * 8 + h] = w1;
        if (lane == 0) g_ms[(b * FL_CH + cy) * Hc + h] = make_float2(m, s);
    }
    __syncthreads();

    // accumulate phase: thread t owns column t, all 64 rows
    unsigned long long acc[4] = {0ull, 0ull, 0ull, 0ull};
    const ulonglong2* wrow = (const ulonglong2*)wsc;
    #pragma unroll 8
    for (int r = 0; r < 64; r++) {
        ulonglong2 w01 = wrow[r * 2];
        ulonglong2 w23 = wrow[r * 2 + 1];
        float e = tile[r * 256 + t];
        unsigned long long ee = f2ull(e, e);
        fma2(acc[0], w01.x, ee);
        fma2(acc[1], w01.y, ee);
        fma2(acc[2], w23.x, ee);
        fma2(acc[3], w23.y, ee);
    }
    #pragma unroll
    for (int hp = 0; hp < 4; hp++) {
        float2 f2v = ull2f2(acc[hp]);
        g_wE_part[cy][(b * Hc + 2 * hp) * Dc + t]     = f2v.x;
        g_wE_part[cy][(b * Hc + 2 * hp + 1) * Dc + t] = f2v.y;
    }
}

// ---------------- fold chain, 4 b's per block, grid 64 ----------------
__global__ void __launch_bounds__(256) k_fold(const float* __restrict__ Wv1,
                                              const float* __restrict__ Wo1,
                                              const float* __restrict__ Wq2,
                                              const float* __restrict__ Wk2) {
    int bs = blockIdx.x * 4, t = threadIdx.x;
    __shared__ float wEs[4][Hc * Dc];   // 32KB
    __shared__ float hos[4][Hc * DHc];  // 4KB
    __shared__ float c2s[4][Dc];        // 4KB
    __shared__ float q2s[4][Dc];        // 4KB
    __shared__ float cf[4][FL_CH][Hc];  // 2KB
    if (t < 32) {
        int bl = t >> 3, h = t & 7;
        float2 ms[FL_CH];
        float M = -1e30f;
        #pragma unroll
        for (int c = 0; c < FL_CH; c++) {
            ms[c] = g_ms[((bs + bl) * FL_CH + c) * Hc + h];
            M = fmaxf(M, ms[c].x);
        }
        float S = 0.f;
        float ef[FL_CH];
        #pragma unroll
        for (int c = 0; c < FL_CH; c++) {
            ef[c] = __expf(ms[c].x - M);
            S += ms[c].y * ef[c];
        }
        float invS = 1.0f / S;
        #pragma unroll
        for (int c = 0; c < FL_CH; c++) cf[bl][c][h] = ef[c] * invS;
    }
    __syncthreads();
    #pragma unroll
    for (int bl = 0; bl < 4; bl++) {
        #pragma unroll
        for (int h = 0; h < Hc; h++) {
            float s = 0.f;
            #pragma unroll
            for (int c = 0; c < FL_CH; c++)
                s += g_wE_part[c][((bs + bl) * Hc + h) * Dc + t] * cf[bl][c][h];
            wEs[bl][h * Dc + t] = s;
        }
    }
    __syncthreads();
    {   // head_out
        int hbase = (t >> 5) * Dc;
        float a0 = 0.f, a1 = 0.f, a2 = 0.f, a3 = 0.f;
        #pragma unroll 4
        for (int i = 0; i < Dc; i++) {
            float w = Wv1[i * Dc + t];
            a0 = fmaf(wEs[0][hbase + i], w, a0);
            a1 = fmaf(wEs[1][hbase + i], w, a1);
            a2 = fmaf(wEs[2][hbase + i], w, a2);
            a3 = fmaf(wEs[3][hbase + i], w, a3);
        }
        hos[0][t] = a0; hos[1][t] = a1; hos[2][t] = a2; hos[3][t] = a3;
    }
    __syncthreads();
    {   // context2
        float a0 = 0.f, a1 = 0.f, a2 = 0.f, a3 = 0.f;
        #pragma unroll 4
        for (int k = 0; k < Hc * DHc; k++) {
            float w = Wo1[k * Dc + t];
            a0 = fmaf(hos[0][k], w, a0);
            a1 = fmaf(hos[1][k], w, a1);
            a2 = fmaf(hos[2][k], w, a2);
            a3 = fmaf(hos[3][k], w, a3);
        }
        c2s[0][t] = a0; c2s[1][t] = a1; c2s[2][t] = a2; c2s[3][t] = a3;
    }
    __syncthreads();
    {   // q2
        float a0 = 0.f, a1 = 0.f, a2 = 0.f, a3 = 0.f;
        #pragma unroll 4
        for (int e = 0; e < Dc; e++) {
            float w = Wq2[e * Dc + t];
            a0 = fmaf(c2s[0][e], w, a0);
            a1 = fmaf(c2s[1][e], w, a1);
            a2 = fmaf(c2s[2][e], w, a2);
            a3 = fmaf(c2s[3][e], w, a3);
        }
        q2s[0][t] = a0; q2s[1][t] = a1; q2s[2][t] = a2; q2s[3][t] = a3;
    }
    __syncthreads();
    {   // qk2[i=t]
        float a0 = 0.f, a1 = 0.f, a2 = 0.f, a3 = 0.f;
        #pragma unroll 4
        for (int j = 0; j < Dc; j++) {
            float w = Wk2[t * Dc + j];
            a0 = fmaf(q2s[0][j], w, a0);
            a1 = fmaf(q2s[1][j], w, a1);
            a2 = fmaf(q2s[2][j], w, a2);
            a3 = fmaf(q2s[3][j], w, a3);
        }
        const float sc = 1.0f / 16.0f;
        g_qk2[(bs + 0) * Dc + t] = a0 * sc;
        g_qk2[(bs + 1) * Dc + t] = a1 * sc;
        g_qk2[(bs + 2) * Dc + t] = a2 * sc;
        g_qk2[(bs + 3) * Dc + t] = a3 * sc;
    }
}

// ---------------- Pass 4a: fs. grid (Bc, 4), 4-row groups with prefetch, fold4 ----------------
__global__ void __launch_bounds__(256, 2) k_fs(const float* __restrict__ ebp,
                                               const int* __restrict__ pa) {
    int b = blockIdx.x, t = threadIdx.x;
    int warp = t >> 5, lane = t & 31;
    int l0 = blockIdx.y * 256;
    __shared__ unsigned mbits[32];
    if (t < 32) mbits[t] = 0u;
    __syncthreads();
    if (t < Tc) {
        int a = pa[b * Tc + t];
        atomicOr(&mbits[a >> 5], 1u << (a & 31));
    }
    __syncthreads();
    unsigned long long qp[4];
    {
        const ulonglong2* qb = (const ulonglong2*)(g_qk2 + b * Dc);
        ulonglong2 u0 = qb[lane * 2], u1 = qb[lane * 2 + 1];
        qp[0] = u0.x; qp[1] = u0.y; qp[2] = u1.x; qp[3] = u1.y;
    }
    int base = l0 + warp;
    ulonglong2 cur[4][2], nxt[4][2];
    #pragma unroll
    for (int i = 0; i < 4; i++) {
        const ulonglong2* p = (const ulonglong2*)(ebp + ((size_t)(base + i * 8) * Bc + b) * Dc) + lane * 2;
        cur[i][0] = p[0]; cur[i][1] = p[1];
    }
    #pragma unroll 2
    for (int g = 0; g < 8; g++) {
        if (g < 7) {
            #pragma unroll
            for (int i = 0; i < 4; i++) {
                const ulonglong2* p = (const ulonglong2*)(ebp + ((size_t)(base + ((g + 1) * 4 + i) * 8) * Bc + b) * Dc) + lane * 2;
                nxt[i][0] = p[0]; nxt[i][1] = p[1];
            }
        }
        float r[4];
        #pragma unroll
        for (int i = 0; i < 4; i++) {
            unsigned long long acc = 0ull;
            fma2(acc, cur[i][0].x, qp[0]);
            fma2(acc, cur[i][0].y, qp[1]);
            fma2(acc, cur[i][1].x, qp[2]);
            fma2(acc, cur[i][1].y, qp[3]);
            float2 f = ull2f2(acc);
            r[i] = f.x + f.y;
        }
        float v = fold4(r, lane);
        if ((lane & 7) == 0) {
            int l = base + (g * 4 + (lane >> 3)) * 8;
            bool m = (mbits[l >> 5] >> (l & 31)) & 1u;
            g_fs[b * Lc + l] = m ? -1e30f : tanhf(v) * 10.0f;
        }
        #pragma unroll
        for (int i = 0; i < 4; i++) { cur[i][0] = nxt[i][0]; cur[i][1] = nxt[i][1]; }
    }
}

// ---------------- Pass 4b: per-b softmax over l (max is 10 by construction) ----------------
__global__ void k_out(float* __restrict__ out) {
    int b = blockIdx.x, t = threadIdx.x;
    int warp = t >> 5, lane = t & 31;
    __shared__ float red[32];
    float v = g_fs[b * Lc + t];
    float e = __expf(v - 10.0f);
    float sm = e;
    #pragma unroll
    for (int o = 16; o > 0; o >>= 1) sm += __shfl_xor_sync(0xffffffffu, sm, o);
    if (lane == 0) red[warp] = sm;
    __syncthreads();
    if (t < 32) {
        float s = red[t];
        #pragma unroll
        for (int o = 16; o > 0; o >>= 1) s += __shfl_xor_sync(0xffffffffu, s, o);
        red[t] = s;
    }
    __syncthreads();
    out[(size_t)t * Bc + b] = e * (1.0f / red[0]);
}

extern "C" void kernel_launch(void* const* d_in, const int* in_sizes, int n_in,
                              void* d_out, int out_size) {
    const float* ebp = (const float*)d_in[0];
    const int*   pa  = (const int*)d_in[1];
    const float* Wq1 = (const float*)d_in[2];
    const float* Wk1 = (const float*)d_in[3];
    const float* Wv1 = (const float*)d_in[4];
    const float* Wo1 = (const float*)d_in[5];
    const float* Wq2 = (const float*)d_in[6];
    const float* Wk2 = (const float*)d_in[7];
    float* out = (float*)d_out;

    static int smem_set = 0;
    const int FLASH_SMEM = 64 * 256 * 4 + 64 * 8 * 4 + 128;  // 67712
    if (!smem_set) {
        cudaFuncSetAttribute(k_flash, cudaFuncAttributeMaxDynamicSharedMemorySize, FLASH_SMEM);
        smem_set = 1;
    }

    dim3 gm(64, MEAN_CH);
    k_mean_part<<<gm, 256>>>(ebp);
    k_q1qk     <<<64, 256>>>(ebp, pa, Wq1, Wk1);
    dim3 gf(Bc, FL_CH);
    k_flash    <<<gf, 256, FLASH_SMEM>>>(ebp, pa);
    k_fold     <<<64, 256>>>(Wv1, Wo1, Wq2, Wk2);
    dim3 gs(Bc, 4);
    k_fs       <<<gs, 256>>>(ebp, pa);
    k_out      <<<Bc, 1024>>>(out);
}

// round 6
// speedup vs baseline: 1.5506x; 1.5506x over previous
#include <cuda_runtime.h>

#define Lc 1024
#define Bc 256
#define Dc 256
#define Tc 50
#define Hc 8
#define DHc 32

#define MEAN_CH 16  // L-chunks for mean pass
#define FL_CH 16    // L-chunks for flash pass (64 rows each)

// Scratch (allocation-free rule: __device__ globals)
__device__ float g_hbar_part[MEAN_CH][Bc*Dc];
__device__ float g_ctx[Bc*3*Dc];                // [b][0..767]
__device__ float g_c1[Bc*Dc];                   // q1
__device__ float g_qk[Bc*Hc*Dc];                // [b][h][i], includes 1/sqrt(32)
__device__ float g_wE_part[FL_CH][Bc*Hc*Dc];    // unnormalized partial [b][h][i]
__device__ float2 g_ms[Bc*FL_CH*Hc];            // (m, s) per (b, chunk, h)
__device__ float g_cf[Bc*Hc*FL_CH];             // combine factors [b][h][c]
__device__ float g_wEn[Bc*Hc*Dc];               // normalized wE
__device__ float g_ho[Bc*Dc];                   // head_out flattened
__device__ float g_c2[Bc*Dc];                   // context2
__device__ float g_q2[Bc*Dc];
__device__ float g_qk2[Bc*Dc];                  // includes 1/16
__device__ float g_fs[Bc*Lc];                   // [b][l]

__device__ __forceinline__ unsigned long long f2ull(float x, float y) {
    unsigned long long u;
    asm("mov.b64 %0, {%1,%2};" : "=l"(u) : "f"(x), "f"(y));
    return u;
}
__device__ __forceinline__ float2 ull2f2(unsigned long long u) {
    float2 f;
    asm("mov.b64 {%0,%1}, %2;" : "=f"(f.x), "=f"(f.y) : "l"(u));
    return f;
}
__device__ __forceinline__ void fma2(unsigned long long& acc, unsigned long long a, unsigned long long b) {
    asm("fma.rn.f32x2 %0, %1, %2, %3;" : "=l"(acc) : "l"(a), "l"(b), "l"(acc));
}
__device__ __forceinline__ void cp_async16(unsigned int saddr, const void* g) {
    asm volatile("cp.async.cg.shared.global [%0], [%1], 16;" :: "r"(saddr), "l"(g));
}

// 8-value fold reduction: lanes with lane%4==0 hold full sum for head (lane>>2). 9 shuffles.
__device__ __forceinline__ float fold8(const float sc[8], int lane) {
    bool hi16 = (lane & 16) != 0;
    float n[4];
    #pragma unroll
    for (int k = 0; k < 4; k++) {
        float give = hi16 ? sc[k] : sc[4 + k];
        float keep = hi16 ? sc[4 + k] : sc[k];
        n[k] = keep + __shfl_xor_sync(0xffffffffu, give, 16);
    }
    bool hi8 = (lane & 8) != 0;
    float m[2];
    #pragma unroll
    for (int j = 0; j < 2; j++) {
        float give = hi8 ? n[j] : n[2 + j];
        float keep = hi8 ? n[2 + j] : n[j];
        m[j] = keep + __shfl_xor_sync(0xffffffffu, give, 8);
    }
    bool hi4 = (lane & 4) != 0;
    float give = hi4 ? m[0] : m[1];
    float keep = hi4 ? m[1] : m[0];
    float v = keep + __shfl_xor_sync(0xffffffffu, give, 4);
    v += __shfl_xor_sync(0xffffffffu, v, 1);
    v += __shfl_xor_sync(0xffffffffu, v, 2);
    return v;
}

// 4-value fold: lanes with lane%8==0 hold row (lane>>3).
__device__ __forceinline__ float fold4(const float r[4], int lane) {
    bool hi16 = (lane & 16) != 0;
    float n[2];
    #pragma unroll
    for (int j = 0; j < 2; j++) {
        float give = hi16 ? r[j] : r[2 + j];
        float keep = hi16 ? r[2 + j] : r[j];
        n[j] = keep + __shfl_xor_sync(0xffffffffu, give, 16);
    }
    bool hi8 = (lane & 8) != 0;
    float give = hi8 ? n[0] : n[1];
    float keep = hi8 ? n[1] : n[0];
    float v = keep + __shfl_xor_sync(0xffffffffu, give, 8);
    v += __shfl_xor_sync(0xffffffffu, v, 4);
    v += __shfl_xor_sync(0xffffffffu, v, 2);
    v += __shfl_xor_sync(0xffffffffu, v, 1);
    return v;
}

// ---------------- Generic 32x32-tile GEMM: C = alpha * A @ B (or A @ B^T) ----------------
// M = 256 (grid.x = 8), N = grid.y * 32. 256 threads, 2x2 microtile per thread.
template<int TRANSB>
__global__ void __launch_bounds__(256) k_gemm(const float* __restrict__ A, int lda, int aSz,
                                              const float* __restrict__ B, int ldb, int bSz,
                                              float* __restrict__ C, int ldc, int cSz,
                                              int K, float alpha) {
    __shared__ float As[32][34];
    __shared__ float Bs[32][34];
    int t = threadIdx.x;
    const float* Ab = A + (size_t)blockIdx.z * aSz + (size_t)(blockIdx.x * 32) * lda;
    const float* Bb = TRANSB ? (B + (size_t)blockIdx.z * bSz + (size_t)(blockIdx.y * 32) * ldb)
                             : (B + (size_t)blockIdx.z * bSz + blockIdx.y * 32);
    float* Cb = C + (size_t)blockIdx.z * cSz + (size_t)(blockIdx.x * 32) * ldc + blockIdx.y * 32;
    int ty = t >> 4, tx = t & 15;
    int r = t >> 3, q = (t & 7) * 4;
    float a00 = 0.f, a01 = 0.f, a10 = 0.f, a11 = 0.f;
    for (int k0 = 0; k0 < K; k0 += 32) {
        float4 av = *(const float4*)(Ab + (size_t)r * lda + k0 + q);
        As[q + 0][r] = av.x; As[q + 1][r] = av.y; As[q + 2][r] = av.z; As[q + 3][r] = av.w;
        if (TRANSB) {
            float4 bv = *(const float4*)(Bb + (size_t)r * ldb + k0 + q);
            Bs[q + 0][r] = bv.x; Bs[q + 1][r] = bv.y; Bs[q + 2][r] = bv.z; Bs[q + 3][r] = bv.w;
        } else {
            float4 bv = *(const float4*)(Bb + (size_t)(k0 + r) * ldb + q);
            Bs[r][q + 0] = bv.x; Bs[r][q + 1] = bv.y; Bs[r][q + 2] = bv.z; Bs[r][q + 3] = bv.w;
        }
        __syncthreads();
        #pragma unroll
        for (int k = 0; k < 32; k++) {
            float2 a = *(const float2*)&As[k][ty * 2];
            float2 b = *(const float2*)&Bs[k][tx * 2];
            a00 = fmaf(a.x, b.x, a00); a01 = fmaf(a.x, b.y, a01);
            a10 = fmaf(a.y, b.x, a10); a11 = fmaf(a.y, b.y, a11);
        }
        __syncthreads();
    }
    Cb[(size_t)(ty * 2) * ldc + tx * 2]     = alpha * a00;
    Cb[(size_t)(ty * 2) * ldc + tx * 2 + 1] = alpha * a01;
    Cb[(size_t)(ty * 2 + 1) * ldc + tx * 2]     = alpha * a10;
    Cb[(size_t)(ty * 2 + 1) * ldc + tx * 2 + 1] = alpha * a11;
}

// ---------------- Pass 1: partial sums for hbar. grid (64, MEAN_CH), block 256 ----------------
__global__ void k_mean_part(const float* __restrict__ ebp) {
    int cg = blockIdx.x * 256 + threadIdx.x;
    int l0 = blockIdx.y * (Lc / MEAN_CH);
    const float4* p = (const float4*)ebp + (size_t)l0 * (Bc * Dc / 4) + cg;
    float4 a0 = {0,0,0,0}, a1 = {0,0,0,0}, a2 = {0,0,0,0}, a3 = {0,0,0,0};
    #pragma unroll 2
    for (int l = 0; l < Lc / MEAN_CH; l += 8) {
        float4 v0 = p[(size_t)(l + 0) * (Bc * Dc / 4)];
        float4 v1 = p[(size_t)(l + 1) * (Bc * Dc / 4)];
        float4 v2 = p[(size_t)(l + 2) * (Bc * Dc / 4)];
        float4 v3 = p[(size_t)(l + 3) * (Bc * Dc / 4)];
        float4 v4 = p[(size_t)(l + 4) * (Bc * Dc / 4)];
        float4 v5 = p[(size_t)(l + 5) * (Bc * Dc / 4)];
        float4 v6 = p[(size_t)(l + 6) * (Bc * Dc / 4)];
        float4 v7 = p[(size_t)(l + 7) * (Bc * Dc / 4)];
        a0.x += v0.x; a0.y += v0.y; a0.z += v0.z; a0.w += v0.w;
        a1.x += v1.x; a1.y += v1.y; a1.z += v1.z; a1.w += v1.w;
        a2.x += v2.x; a2.y += v2.y; a2.z += v2.z; a2.w += v2.w;
        a3.x += v3.x; a3.y += v3.y; a3.z += v3.z; a3.w += v3.w;
        a0.x += v4.x; a0.y += v4.y; a0.z += v4.z; a0.w += v4.w;
        a1.x += v5.x; a1.y += v5.y; a1.z += v5.z; a1.w += v5.w;
        a2.x += v6.x; a2.y += v6.y; a2.z += v6.z; a2.w += v6.w;
        a3.x += v7.x; a3.y += v7.y; a3.z += v7.z; a3.w += v7.w;
    }
    float4 r;
    r.x = (a0.x + a1.x) + (a2.x + a3.x);
    r.y = (a0.y + a1.y) + (a2.y + a3.y);
    r.z = (a0.z + a1.z) + (a2.z + a3.z);
    r.w = (a0.w + a1.w) + (a2.w + a3.w);
    ((float4*)g_hbar_part[blockIdx.y])[cg] = r;
}

// ---------------- ctx assembly: [hbar, prev_emb, first_emb] per b. grid 256 ----------------
__global__ void k_ctx(const float* __restrict__ ebp, const int* __restrict__ pa) {
    int b = blockIdx.x, t = threadIdx.x;
    float hs = 0.f;
    #pragma unroll
    for (int c = 0; c < MEAN_CH; c++) hs += g_hbar_part[c][b * Dc + t];
    g_ctx[b * 3 * Dc + t] = hs * (1.0f / Lc);
    int aL = pa[b * Tc + (Tc - 1)];
    int a0 = pa[b * Tc];
    g_ctx[b * 3 * Dc + Dc + t]     = ebp[((size_t)aL * Bc + b) * Dc + t];
    g_ctx[b * 3 * Dc + 2 * Dc + t] = ebp[((size_t)a0 * Bc + b) * Dc + t];
}

// ---------------- Fused flash pass (unchanged from R5) ----------------
__global__ void __launch_bounds__(256, 2) k_flash(const float* __restrict__ ebp,
                                                  const int* __restrict__ pa) {
    extern __shared__ float smem[];
    float* tile = smem;                       // [64][256]
    float* wsc  = smem + 64 * 256;            // [64][8]
    unsigned* mb = (unsigned*)(wsc + 64 * 8);
    int b = blockIdx.x, cy = blockIdx.y, t = threadIdx.x;
    int warp = t >> 5, lane = t & 31;
    int l0 = cy * 64;

    if (t < 32) mb[t] = 0u;
    {
        int r = t >> 2, part = t & 3;
        const float* grow = ebp + ((size_t)(l0 + r) * Bc + b) * Dc + part * 64;
        unsigned int sa = (unsigned int)__cvta_generic_to_shared(tile + r * 256 + part * 64);
        #pragma unroll
        for (int k = 0; k < 16; k++) cp_async16(sa + k * 16, grow + k * 4);
        asm volatile("cp.async.commit_group;");
    }
    __syncthreads();
    if (t < Tc) {
        int a = pa[b * Tc + t];
        atomicOr(&mb[a >> 5], 1u << (a & 31));
    }

    unsigned long long qkp[Hc][4];
    {
        const ulonglong2* qb = (const ulonglong2*)(g_qk + b * Hc * Dc);
        #pragma unroll
        for (int h = 0; h < Hc; h++) {
            ulonglong2 u0 = qb[h * (Dc / 4) + lane * 2];
            ulonglong2 u1 = qb[h * (Dc / 4) + lane * 2 + 1];
            qkp[h][0] = u0.x; qkp[h][1] = u0.y; qkp[h][2] = u1.x; qkp[h][3] = u1.y;
        }
    }
    asm volatile("cp.async.wait_group 0;" ::: "memory");
    __syncthreads();

    #pragma unroll
    for (int j = 0; j < 8; j++) {
        int r = warp * 8 + j;
        const ulonglong2* rp = (const ulonglong2*)(tile + r * 256) + lane * 2;
        ulonglong2 A = rp[0], B = rp[1];
        unsigned long long e[4] = {A.x, A.y, B.x, B.y};
        float sc[Hc];
        #pragma unroll
        for (int h = 0; h < Hc; h++) {
            unsigned long long acc = 0ull;
            #pragma unroll
            for (int q = 0; q < 4; q++) fma2(acc, e[q], qkp[h][q]);
            float2 f = ull2f2(acc);
            sc[h] = f.x + f.y;
        }
        float v = fold8(sc, lane);
        if ((lane & 3) == 0) {
            int h = lane >> 2;
            int l = l0 + r;
            bool m = (mb[l >> 5] >> (l & 31)) & 1u;
            wsc[r * 8 + h] = m ? -1e4f : v;
        }
    }
    __syncthreads();

    if (warp < 8) {
        int h = warp;
        float lv0 = wsc[lane * 8 + h];
        float lv1 = wsc[(lane + 32) * 8 + h];
        float m = fmaxf(lv0, lv1);
        #pragma unroll
        for (int o = 16; o > 0; o >>= 1) m = fmaxf(m, __shfl_xor_sync(0xffffffffu, m, o));
        float w0 = __expf(lv0 - m), w1 = __expf(lv1 - m);
        float s = w0 + w1;
        #pragma unroll
        for (int o = 16; o > 0; o >>= 1) s += __shfl_xor_sync(0xffffffffu, s, o);
        wsc[lane * 8 + h] = w0;
        wsc[(lane + 32) * 8 + h] = w1;
        if (lane == 0) g_ms[(b * FL_CH + cy) * Hc + h] = make_float2(m, s);
    }
    __syncthreads();

    unsigned long long acc[4] = {0ull, 0ull, 0ull, 0ull};
    const ulonglong2* wrow = (const ulonglong2*)wsc;
    #pragma unroll 8
    for (int r = 0; r < 64; r++) {
        ulonglong2 w01 = wrow[r * 2];
        ulonglong2 w23 = wrow[r * 2 + 1];
        float e = tile[r * 256 + t];
        unsigned long long ee = f2ull(e, e);
        fma2(acc[0], w01.x, ee);
        fma2(acc[1], w01.y, ee);
        fma2(acc[2], w23.x, ee);
        fma2(acc[3], w23.y, ee);
    }
    #pragma unroll
    for (int hp = 0; hp < 4; hp++) {
        float2 f2v = ull2f2(acc[hp]);
        g_wE_part[cy][(b * Hc + 2 * hp) * Dc + t]     = f2v.x;
        g_wE_part[cy][(b * Hc + 2 * hp + 1) * Dc + t] = f2v.y;
    }
}

// ---------------- cf: per (b,h) chunk-combine factors. grid 8, block 256 ----------------
__global__ void k_cf() {
    int idx = blockIdx.x * 256 + threadIdx.x;   // b*8 + h
    int b = idx >> 3, h = idx & 7;
    float2 ms[FL_CH];
    float M = -1e30f;
    #pragma unroll
    for (int c = 0; c < FL_CH; c++) {
        ms[c] = g_ms[(b * FL_CH + c) * Hc + h];
        M = fmaxf(M, ms[c].x);
    }
    float S = 0.f;
    float ef[FL_CH];
    #pragma unroll
    for (int c = 0; c < FL_CH; c++) {
        ef[c] = __expf(ms[c].x - M);
        S += ms[c].y * ef[c];
    }
    float invS = 1.0f / S;
    #pragma unroll
    for (int c = 0; c < FL_CH; c++) g_cf[(b * Hc + h) * FL_CH + c] = ef[c] * invS;
}

// ---------------- combine: wEn[b,h,i] = sum_c wE_part[c]*cf. grid 2048, block 256 ----------------
__global__ void k_combine() {
    int bh = blockIdx.x, i = threadIdx.x;
    const float* cfp = g_cf + bh * FL_CH;
    float s = 0.f;
    #pragma unroll
    for (int c = 0; c < FL_CH; c++)
        s += g_wE_part[c][bh * Dc + i] * cfp[c];
    g_wEn[bh * Dc + i] = s;
}

// ---------------- Pass 4a: fs. grid (Bc, 4) (unchanged) ----------------
__global__ void __launch_bounds__(256, 2) k_fs(const float* __restrict__ ebp,
                                               const int* __restrict__ pa) {
    int b = blockIdx.x, t = threadIdx.x;
    int warp = t >> 5, lane = t & 31;
    int l0 = blockIdx.y * 256;
    __shared__ unsigned mbits[32];
    if (t < 32) mbits[t] = 0u;
    __syncthreads();
    if (t < Tc) {
        int a = pa[b * Tc + t];
        atomicOr(&mbits[a >> 5], 1u << (a & 31));
    }
    __syncthreads();
    unsigned long long qp[4];
    {
        const ulonglong2* qb = (const ulonglong2*)(g_qk2 + b * Dc);
        ulonglong2 u0 = qb[lane * 2], u1 = qb[lane * 2 + 1];
        qp[0] = u0.x; qp[1] = u0.y; qp[2] = u1.x; qp[3] = u1.y;
    }
    int base = l0 + warp;
    ulonglong2 cur[4][2], nxt[4][2];
    #pragma unroll
    for (int i = 0; i < 4; i++) {
        const ulonglong2* p = (const ulonglong2*)(ebp + ((size_t)(base + i * 8) * Bc + b) * Dc) + lane * 2;
        cur[i][0] = p[0]; cur[i][1] = p[1];
    }
    #pragma unroll 2
    for (int g = 0; g < 8; g++) {
        if (g < 7) {
            #pragma unroll
            for (int i = 0; i < 4; i++) {
                const ulonglong2* p = (const ulonglong2*)(ebp + ((size_t)(base + ((g + 1) * 4 + i) * 8) * Bc + b) * Dc) + lane * 2;
                nxt[i][0] = p[0]; nxt[i][1] = p[1];
            }
        }
        float r[4];
        #pragma unroll
        for (int i = 0; i < 4; i++) {
            unsigned long long acc = 0ull;
            fma2(acc, cur[i][0].x, qp[0]);
            fma2(acc, cur[i][0].y, qp[1]);
            fma2(acc, cur[i][1].x, qp[2]);
            fma2(acc, cur[i][1].y, qp[3]);
            float2 f = ull2f2(acc);
            r[i] = f.x + f.y;
        }
        float v = fold4(r, lane);
        if ((lane & 7) == 0) {
            int l = base + (g * 4 + (lane >> 3)) * 8;
            bool m = (mbits[l >> 5] >> (l & 31)) & 1u;
            g_fs[b * Lc + l] = m ? -1e30f : tanhf(v) * 10.0f;
        }
        #pragma unroll
        for (int i = 0; i < 4; i++) { cur[i][0] = nxt[i][0]; cur[i][1] = nxt[i][1]; }
    }
}

// ---------------- Pass 4b: per-b softmax over l ----------------
__global__ void k_out(float* __restrict__ out) {
    int b = blockIdx.x, t = threadIdx.x;
    int warp = t >> 5, lane = t & 31;
    __shared__ float red[32];
    float v = g_fs[b * Lc + t];
    float e = __expf(v - 10.0f);
    float sm = e;
    #pragma unroll
    for (int o = 16; o > 0; o >>= 1) sm += __shfl_xor_sync(0xffffffffu, sm, o);
    if (lane == 0) red[warp] = sm;
    __syncthreads();
    if (t < 32) {
        float s = red[t];
        #pragma unroll
        for (int o = 16; o > 0; o >>= 1) s += __shfl_xor_sync(0xffffffffu, s, o);
        red[t] = s;
    }
    __syncthreads();
    out[(size_t)t * Bc + b] = e * (1.0f / red[0]);
}

extern "C" void kernel_launch(void* const* d_in, const int* in_sizes, int n_in,
                              void* d_out, int out_size) {
    const float* ebp = (const float*)d_in[0];
    const int*   pa  = (const int*)d_in[1];
    const float* Wq1 = (const float*)d_in[2];
    const float* Wk1 = (const float*)d_in[3];
    const float* Wv1 = (const float*)d_in[4];
    const float* Wo1 = (const float*)d_in[5];
    const float* Wq2 = (const float*)d_in[6];
    const float* Wk2 = (const float*)d_in[7];
    float* out = (float*)d_out;

    static int smem_set = 0;
    const int FLASH_SMEM = 64 * 256 * 4 + 64 * 8 * 4 + 128;  // 67712
    if (!smem_set) {
        cudaFuncSetAttribute(k_flash, cudaFuncAttributeMaxDynamicSharedMemorySize, FLASH_SMEM);
        smem_set = 1;
    }

    float* d_ctx;  cudaGetSymbolAddress((void**)&d_ctx,  g_ctx);
    float* d_c1;   cudaGetSymbolAddress((void**)&d_c1,   g_c1);
    float* d_qk;   cudaGetSymbolAddress((void**)&d_qk,   g_qk);
    float* d_wEn;  cudaGetSymbolAddress((void**)&d_wEn,  g_wEn);
    float* d_ho;   cudaGetSymbolAddress((void**)&d_ho,   g_ho);
    float* d_c2;   cudaGetSymbolAddress((void**)&d_c2,   g_c2);
    float* d_q2;   cudaGetSymbolAddress((void**)&d_q2,   g_q2);
    float* d_qk2;  cudaGetSymbolAddress((void**)&d_qk2,  g_qk2);

    dim3 gm(64, MEAN_CH);
    k_mean_part<<<gm, 256>>>(ebp);
    k_ctx<<<Bc, 256>>>(ebp, pa);

    // q1 = ctx(256x768) @ Wq1(768x256)
    k_gemm<0><<<dim3(8, 8, 1), 256>>>(d_ctx, 3 * Dc, 0, Wq1, Dc, 0,
                                      d_c1, Dc, 0, 3 * Dc, 1.0f);
    // qk[b,h,i] = q1[b, h*32+d] . Wk1[i, h*32+d]  (A @ B^T per head)
    k_gemm<1><<<dim3(8, 8, Hc), 256>>>(d_c1, Dc, DHc, Wk1, Dc, DHc,
                                       d_qk, Hc * Dc, Dc, DHc, 0.17677669529663687f);

    dim3 gf(Bc, FL_CH);
    k_flash<<<gf, 256, FLASH_SMEM>>>(ebp, pa);
    k_cf<<<8, 256>>>();
    k_combine<<<Bc * Hc, 256>>>();

    // head_out[b, h*32+d] = wEn[b,h,i] . Wv1[i, h*32+d]   (per head, N=32)
    k_gemm<0><<<dim3(8, 1, Hc), 256>>>(d_wEn, Hc * Dc, Dc, Wv1, Dc, DHc,
                                       d_ho, Dc, DHc, Dc, 1.0f);
    // context2 = ho(256x256) @ Wo1(256x256)
    k_gemm<0><<<dim3(8, 8, 1), 256>>>(d_ho, Dc, 0, Wo1, Dc, 0,
                                      d_c2, Dc, 0, Dc, 1.0f);
    // q2 = c2 @ Wq2
    k_gemm<0><<<dim3(8, 8, 1), 256>>>(d_c2, Dc, 0, Wq2, Dc, 0,
                                      d_q2, Dc, 0, Dc, 1.0f);
    // qk2 = (1/16) q2 @ Wk2^T
    k_gemm<1><<<dim3(8, 8, 1), 256>>>(d_q2, Dc, 0, Wk2, Dc, 0,
                                      d_qk2, Dc, 0, Dc, 1.0f / 16.0f);

    dim3 gs(Bc, 4);
    k_fs<<<gs, 256>>>(ebp, pa);
    k_out<<<Bc, 1024>>>(out);
}